// round 1
// baseline (speedup 1.0000x reference)
#include <cuda_runtime.h>

// ---------------------------------------------------------------------------
// StyleBlock: upsample2x(bilinear, half-pixel) -> modconv 512->256 3x3 (demod)
//             -> lrelu -> modconv 256->256 3x3 (demod) -> lrelu = h
//             -> 1x1 to_rgb (no demod) -> lrelu = rgb
// Key identity: modulation = per-(b,ci) input scale, demod = per-(b,co) output
// scale => convs use SHARED weights across batch (standard batched conv).
// ---------------------------------------------------------------------------

#define LRELU 0.2f
#define BATCH 4
#define CIN1 512
#define CMID 256
#define HW 128
#define NPIX (HW * HW)   // 16384
#define H0 64

// ------------------------------ scratch ------------------------------------
__device__ float g_xu[BATCH * CIN1 * NPIX];     // upsampled + s1-scaled input (134 MB)
__device__ float g_h1[BATCH * CMID * NPIX];     // conv1 output (pre-scaled by s2) (67 MB)
__device__ float g_wT1[CIN1 * 9 * CMID];        // w1 transposed to [(ci*9+k)][co]
__device__ float g_wT2[CMID * 9 * CMID];        // w2 transposed
__device__ float g_s1[BATCH * CIN1];
__device__ float g_s2[BATCH * CMID];
__device__ float g_s3[BATCH * CMID];
__device__ float g_d1[BATCH * CMID];
__device__ float g_d2[BATCH * CMID];
__device__ float g_wm3[BATCH * 3 * CMID];       // w3[co][ci]*s3[b][ci]

// ------------------------------ styles -------------------------------------
__global__ void styles_kernel(const float* __restrict__ w,
                              const float* __restrict__ a1w, const float* __restrict__ a1b,
                              const float* __restrict__ a2w, const float* __restrict__ a2b,
                              const float* __restrict__ a3w, const float* __restrict__ a3b,
                              const float* __restrict__ w3)
{
    __shared__ float wv[512];
    __shared__ float s3s[256];
    const int b = blockIdx.x;
    const int t = threadIdx.x;
    wv[t] = w[b * 512 + t];
    __syncthreads();
    {
        float acc = 0.f;
        const float* row = a1w + t * 512;
        for (int j = 0; j < 512; j++) acc += wv[j] * row[j];
        g_s1[b * CIN1 + t] = acc + a1b[t];
    }
    if (t < 256) {
        float acc = 0.f;
        const float* row = a2w + t * 512;
        for (int j = 0; j < 512; j++) acc += wv[j] * row[j];
        g_s2[b * CMID + t] = acc + a2b[t];
        acc = 0.f;
        row = a3w + t * 512;
        for (int j = 0; j < 512; j++) acc += wv[j] * row[j];
        float sv = acc + a3b[t];
        g_s3[b * CMID + t] = sv;
        s3s[t] = sv;
    }
    __syncthreads();
    if (t < 256) {
#pragma unroll
        for (int co = 0; co < 3; co++)
            g_wm3[(b * 3 + co) * CMID + t] = w3[co * CMID + t] * s3s[t];
    }
}

// -------------------------- demod factors ----------------------------------
// d[b,co] = rsqrt( sum_ci s[b,ci]^2 * sum_k w[co,ci,k]^2 + 1e-8 )
template <int CIN>
__global__ void demod_kernel(const float* __restrict__ w)
{
    const float* s = (CIN == 512) ? g_s1 : g_s2;
    float* d = (CIN == 512) ? g_d1 : g_d2;
    __shared__ float red[256];
    const int co = blockIdx.x;
    const int b = blockIdx.y;
    const int t = threadIdx.x;
    float tot = 0.f;
    for (int ci = t; ci < CIN; ci += 256) {
        const float* wp = w + (co * CIN + ci) * 9;
        float ws = 0.f;
#pragma unroll
        for (int k = 0; k < 9; k++) ws += wp[k] * wp[k];
        float sv = s[b * CIN + ci];
        tot += ws * sv * sv;
    }
    red[t] = tot;
    __syncthreads();
    for (int o = 128; o > 0; o >>= 1) {
        if (t < o) red[t] += red[t + o];
        __syncthreads();
    }
    if (t == 0) d[b * CMID + co] = rsqrtf(red[0] + 1e-8f);
}

// ------------------------- weight transpose --------------------------------
// wT[(ci*9+k)*256 + co] = w[co][ci][k]
template <int CIN>
__global__ void wtrans_kernel(const float* __restrict__ w)
{
    float* wT = (CIN == 512) ? g_wT1 : g_wT2;
    int idx = blockIdx.x * 256 + threadIdx.x;
    if (idx >= CMID * CIN * 9) return;
    int co = idx / (CIN * 9);
    int r = idx - co * (CIN * 9);
    int ci = r / 9;
    int k = r - ci * 9;
    wT[(ci * 9 + k) * CMID + co] = w[idx];
}

// -------------------- upsample (half-pixel bilinear) + s1 scale ------------
__global__ void upsample_kernel(const float* __restrict__ x)
{
    int idx = blockIdx.x * 256 + threadIdx.x;   // < 2^25
    int xo = idx & 127;
    int yo = (idx >> 7) & 127;
    int c = (idx >> 14) & 511;
    int b = idx >> 23;
    int j = yo >> 1, i = xo >> 1;
    int y0, y1, x0, x1;
    float wy0, wy1, wx0, wx1;
    if (yo & 1) { y0 = j; y1 = min(j + 1, 63); wy0 = 0.75f; wy1 = 0.25f; }
    else        { y0 = max(j - 1, 0); y1 = j;  wy0 = 0.25f; wy1 = 0.75f; }
    if (xo & 1) { x0 = i; x1 = min(i + 1, 63); wx0 = 0.75f; wx1 = 0.25f; }
    else        { x0 = max(i - 1, 0); x1 = i;  wx0 = 0.25f; wx1 = 0.75f; }
    const float* p = x + (b * CIN1 + c) * (H0 * H0);
    float v = wy0 * (wx0 * p[y0 * H0 + x0] + wx1 * p[y0 * H0 + x1]) +
              wy1 * (wx0 * p[y1 * H0 + x0] + wx1 * p[y1 * H0 + x1]);
    g_xu[idx] = v * g_s1[b * CIN1 + c];
}

// ------------------------------ conv 3x3 -----------------------------------
// Block: 128 cout x 128 pixels (one image row). 256 threads, 8x8 acc/thread.
// cp.async double-buffered smem: input rows [BC][3][136] + weights [BC*9][128].
constexpr int TCO = 128;
constexpr int BC = 4;
constexpr int INSTRIDE = 136;
constexpr int INSZ = BC * 3 * INSTRIDE;   // 1632 floats
constexpr int WSZ = BC * 9 * TCO;         // 4608 floats
constexpr int BUFSZ = INSZ + WSZ;         // 6240 floats
constexpr int CONV_SMEM_BYTES = 2 * BUFSZ * 4;  // 49,920 B

__device__ __forceinline__ void cp_async16(float* dst, const float* src)
{
    unsigned da = (unsigned)__cvta_generic_to_shared(dst);
    asm volatile("cp.async.cg.shared.global [%0], [%1], 16;\n" ::"r"(da), "l"(src));
}

template <int CIN>
__global__ void __launch_bounds__(256)
conv3x3_kernel(const float* __restrict__ bias, float* __restrict__ outArg)
{
    const float* in = (CIN == 512) ? g_xu : g_h1;
    const float* wT = (CIN == 512) ? g_wT1 : g_wT2;
    const float* dsc = (CIN == 512) ? g_d1 : g_d2;
    const float* postScale = (CIN == 512) ? g_s2 : nullptr;  // fold s2 into conv1 epilogue
    float* out = (CIN == 512) ? g_h1 : outArg;

    extern __shared__ float smem[];
    const int t = threadIdx.x;
    const int b = blockIdx.z;
    const int coBase = blockIdx.y * TCO;
    const int y = blockIdx.x;
    const int tco = t >> 4;          // 0..15 -> 8 couts each
    const int px0 = (t & 15) * 8;    // 8 pixels each

    // permanent zero pad (img cols -1 and 128), both buffers
    if (t < 48) {
        int e = t;
        int bufi = e & 1; e >>= 1;
        int side = e & 1; e >>= 1;            // e: 0..11 = cil*3+r
        smem[bufi * BUFSZ + e * INSTRIDE + (side ? 132 : 3)] = 0.f;
    }

    const float* inB = in + (b * CIN) * NPIX;

    auto fill = [&](int buf, int chunk) {
        const int ciBase = chunk * BC;
        float* bin = smem + buf * BUFSZ;
        float* bwt = bin + INSZ;
        // input rows: BC*3 rows x 32 float4 (img cols 0..127 -> smem idx 4..131)
        for (int s = t; s < BC * 3 * 32; s += 256) {
            int cil = s / 96;
            int rem = s - cil * 96;
            int r = rem >> 5;
            int q = rem & 31;
            int yr = y - 1 + r;
            float* dst = bin + (cil * 3 + r) * INSTRIDE + 4 + q * 4;
            if ((unsigned)yr < (unsigned)HW) {
                const float* src = inB + ((ciBase + cil) * HW + yr) * HW + q * 4;
                cp_async16(dst, src);
            } else {
                *(float4*)dst = make_float4(0.f, 0.f, 0.f, 0.f);
            }
        }
        // weights: 36 rows x 32 float4 (fully coalesced from transposed layout)
        const float* wB = wT + (ciBase * 9) * CMID + coBase;
        for (int s = t; s < BC * 9 * 32; s += 256) {
            int row = s >> 5;
            int q = s & 31;
            cp_async16(bwt + row * TCO + q * 4, wB + row * CMID + q * 4);
        }
    };

    float acc[8][8];
#pragma unroll
    for (int i = 0; i < 8; i++)
#pragma unroll
        for (int j = 0; j < 8; j++) acc[i][j] = 0.f;

    constexpr int NCH = CIN / BC;
    fill(0, 0);
    asm volatile("cp.async.commit_group;\n");

    for (int c = 0; c < NCH; ++c) {
        const int cur = c & 1;
        if (c + 1 < NCH) {
            fill(cur ^ 1, c + 1);
            asm volatile("cp.async.commit_group;\n");
            asm volatile("cp.async.wait_group 1;\n");
        } else {
            asm volatile("cp.async.wait_group 0;\n");
        }
        __syncthreads();

        const float* bin = smem + cur * BUFSZ;
        const float* bwt = bin + INSZ;
#pragma unroll
        for (int cil = 0; cil < BC; cil++) {
#pragma unroll
            for (int r = 0; r < 3; r++) {
                const float* ip = bin + (cil * 3 + r) * INSTRIDE + px0 + 3;
                float4 xa = *(const float4*)(ip + 1);
                float4 xb = *(const float4*)(ip + 5);
                float x10[10] = {ip[0], xa.x, xa.y, xa.z, xa.w,
                                 xb.x, xb.y, xb.z, xb.w, ip[9]};
#pragma unroll
                for (int kc = 0; kc < 3; kc++) {
                    const float* wp = bwt + (cil * 9 + r * 3 + kc) * TCO + tco * 8;
                    float4 wa = *(const float4*)(wp);
                    float4 wb = *(const float4*)(wp + 4);
                    float w8[8] = {wa.x, wa.y, wa.z, wa.w, wb.x, wb.y, wb.z, wb.w};
#pragma unroll
                    for (int i = 0; i < 8; i++)
#pragma unroll
                        for (int j = 0; j < 8; j++)
                            acc[i][j] += w8[i] * x10[j + kc];
                }
            }
        }
        __syncthreads();
    }

    // epilogue: demod scale + bias + lrelu (+ optional post-scale for next conv)
#pragma unroll
    for (int i = 0; i < 8; i++) {
        int co = coBase + tco * 8 + i;
        float dv = dsc[b * CMID + co];
        float bv = bias[co];
        float ps = (postScale != nullptr) ? postScale[b * CMID + co] : 1.f;
        float o[8];
#pragma unroll
        for (int j = 0; j < 8; j++) {
            float v = acc[i][j] * dv + bv;
            v = v > 0.f ? v : LRELU * v;
            o[j] = v * ps;
        }
        float* op = out + ((b * CMID + co) * HW + y) * HW + px0;
        *(float4*)op = make_float4(o[0], o[1], o[2], o[3]);
        *(float4*)(op + 4) = make_float4(o[4], o[5], o[6], o[7]);
    }
}

// ------------------------------ to_rgb 1x1 ---------------------------------
__global__ void rgb_kernel(const float* __restrict__ h, const float* __restrict__ b3,
                           float* __restrict__ rgb)
{
    __shared__ float wm[3 * 256];
    const int b = blockIdx.y;
    const int t = threadIdx.x;
    const int p = blockIdx.x * 256 + t;
    wm[t] = g_wm3[b * 768 + t];
    wm[256 + t] = g_wm3[b * 768 + 256 + t];
    wm[512 + t] = g_wm3[b * 768 + 512 + t];
    __syncthreads();
    float a0 = b3[0], a1 = b3[1], a2 = b3[2];
    const float* hp = h + (b * CMID) * NPIX + p;
#pragma unroll 4
    for (int ci = 0; ci < CMID; ci++) {
        float v = hp[ci * NPIX];
        a0 += wm[ci] * v;
        a1 += wm[256 + ci] * v;
        a2 += wm[512 + ci] * v;
    }
    a0 = a0 > 0.f ? a0 : LRELU * a0;
    a1 = a1 > 0.f ? a1 : LRELU * a1;
    a2 = a2 > 0.f ? a2 : LRELU * a2;
    rgb[(b * 3 + 0) * NPIX + p] = a0;
    rgb[(b * 3 + 1) * NPIX + p] = a1;
    rgb[(b * 3 + 2) * NPIX + p] = a2;
}

// ------------------------------ launch -------------------------------------
extern "C" void kernel_launch(void* const* d_in, const int* in_sizes, int n_in,
                              void* d_out, int out_size)
{
    const float* x   = (const float*)d_in[0];
    const float* w   = (const float*)d_in[1];
    const float* w1  = (const float*)d_in[2];
    const float* b1  = (const float*)d_in[3];
    const float* a1w = (const float*)d_in[4];
    const float* a1b = (const float*)d_in[5];
    const float* w2  = (const float*)d_in[6];
    const float* b2  = (const float*)d_in[7];
    const float* a2w = (const float*)d_in[8];
    const float* a2b = (const float*)d_in[9];
    const float* w3  = (const float*)d_in[10];
    const float* b3  = (const float*)d_in[11];
    const float* a3w = (const float*)d_in[12];
    const float* a3b = (const float*)d_in[13];

    float* h_out = (float*)d_out;
    float* rgb_out = h_out + BATCH * CMID * NPIX;

    cudaFuncSetAttribute(conv3x3_kernel<512>, cudaFuncAttributeMaxDynamicSharedMemorySize,
                         CONV_SMEM_BYTES);
    cudaFuncSetAttribute(conv3x3_kernel<256>, cudaFuncAttributeMaxDynamicSharedMemorySize,
                         CONV_SMEM_BYTES);

    styles_kernel<<<BATCH, 512>>>(w, a1w, a1b, a2w, a2b, a3w, a3b, w3);
    demod_kernel<512><<<dim3(CMID, BATCH), 256>>>(w1);
    demod_kernel<256><<<dim3(CMID, BATCH), 256>>>(w2);
    wtrans_kernel<512><<<(CMID * 512 * 9) / 256, 256>>>(w1);
    wtrans_kernel<256><<<(CMID * 256 * 9) / 256, 256>>>(w2);
    upsample_kernel<<<(BATCH * CIN1 * NPIX) / 256, 256>>>(x);

    conv3x3_kernel<512><<<dim3(HW, CMID / TCO, BATCH), 256, CONV_SMEM_BYTES>>>(b1, nullptr);
    conv3x3_kernel<256><<<dim3(HW, CMID / TCO, BATCH), 256, CONV_SMEM_BYTES>>>(b2, h_out);

    rgb_kernel<<<dim3(NPIX / 256, BATCH), 256>>>(h_out, b3, rgb_out);
}

// round 2
// speedup vs baseline: 1.0005x; 1.0005x over previous
#include <cuda_runtime.h>

// ---------------------------------------------------------------------------
// StyleBlock: upsample2x(bilinear, half-pixel) -> modconv 512->256 3x3 (demod)
//             -> lrelu -> modconv 256->256 3x3 (demod) -> lrelu = h
//             -> 1x1 to_rgb (no demod) -> lrelu = rgb
// Key identity: modulation = per-(b,ci) input scale, demod = per-(b,co) output
// scale => convs use SHARED weights across batch (standard batched conv).
// ---------------------------------------------------------------------------

#define LRELU 0.2f
#define BATCH 4
#define CIN1 512
#define CMID 256
#define HW 128
#define NPIX (HW * HW)   // 16384
#define H0 64

// ------------------------------ scratch ------------------------------------
__device__ float g_xu[BATCH * CIN1 * NPIX];     // upsampled + s1-scaled input (134 MB)
__device__ float g_h1[BATCH * CMID * NPIX];     // conv1 output (pre-scaled by s2) (67 MB)
__device__ float g_wT1[CIN1 * 9 * CMID];        // w1 transposed to [(ci*9+k)][co]
__device__ float g_wT2[CMID * 9 * CMID];        // w2 transposed
__device__ float g_s1[BATCH * CIN1];
__device__ float g_s2[BATCH * CMID];
__device__ float g_s3[BATCH * CMID];
__device__ float g_d1[BATCH * CMID];
__device__ float g_d2[BATCH * CMID];
__device__ float g_wm3[BATCH * 3 * CMID];       // w3[co][ci]*s3[b][ci]

// ------------------------------ styles -------------------------------------
__global__ void styles_kernel(const float* __restrict__ w,
                              const float* __restrict__ a1w, const float* __restrict__ a1b,
                              const float* __restrict__ a2w, const float* __restrict__ a2b,
                              const float* __restrict__ a3w, const float* __restrict__ a3b,
                              const float* __restrict__ w3)
{
    __shared__ float wv[512];
    __shared__ float s3s[256];
    const int b = blockIdx.x;
    const int t = threadIdx.x;
    wv[t] = w[b * 512 + t];
    __syncthreads();
    {
        float acc = 0.f;
        const float* row = a1w + t * 512;
        for (int j = 0; j < 512; j++) acc += wv[j] * row[j];
        g_s1[b * CIN1 + t] = acc + a1b[t];
    }
    if (t < 256) {
        float acc = 0.f;
        const float* row = a2w + t * 512;
        for (int j = 0; j < 512; j++) acc += wv[j] * row[j];
        g_s2[b * CMID + t] = acc + a2b[t];
        acc = 0.f;
        row = a3w + t * 512;
        for (int j = 0; j < 512; j++) acc += wv[j] * row[j];
        float sv = acc + a3b[t];
        g_s3[b * CMID + t] = sv;
        s3s[t] = sv;
    }
    __syncthreads();
    if (t < 256) {
#pragma unroll
        for (int co = 0; co < 3; co++)
            g_wm3[(b * 3 + co) * CMID + t] = w3[co * CMID + t] * s3s[t];
    }
}

// -------------------------- demod factors ----------------------------------
// d[b,co] = rsqrt( sum_ci s[b,ci]^2 * sum_k w[co,ci,k]^2 + 1e-8 )
template <int CIN>
__global__ void demod_kernel(const float* __restrict__ w)
{
    const float* s = (CIN == 512) ? g_s1 : g_s2;
    float* d = (CIN == 512) ? g_d1 : g_d2;
    __shared__ float red[256];
    const int co = blockIdx.x;
    const int b = blockIdx.y;
    const int t = threadIdx.x;
    float tot = 0.f;
    for (int ci = t; ci < CIN; ci += 256) {
        const float* wp = w + (co * CIN + ci) * 9;
        float ws = 0.f;
#pragma unroll
        for (int k = 0; k < 9; k++) ws += wp[k] * wp[k];
        float sv = s[b * CIN + ci];
        tot += ws * sv * sv;
    }
    red[t] = tot;
    __syncthreads();
    for (int o = 128; o > 0; o >>= 1) {
        if (t < o) red[t] += red[t + o];
        __syncthreads();
    }
    if (t == 0) d[b * CMID + co] = rsqrtf(red[0] + 1e-8f);
}

// ------------------------- weight transpose --------------------------------
// wT[(ci*9+k)*256 + co] = w[co][ci][k]
template <int CIN>
__global__ void wtrans_kernel(const float* __restrict__ w)
{
    float* wT = (CIN == 512) ? g_wT1 : g_wT2;
    int idx = blockIdx.x * 256 + threadIdx.x;
    if (idx >= CMID * CIN * 9) return;
    int co = idx / (CIN * 9);
    int r = idx - co * (CIN * 9);
    int ci = r / 9;
    int k = r - ci * 9;
    wT[(ci * 9 + k) * CMID + co] = w[idx];
}

// -------------------- upsample (half-pixel bilinear) + s1 scale ------------
__global__ void upsample_kernel(const float* __restrict__ x)
{
    int idx = blockIdx.x * 256 + threadIdx.x;   // < 2^25
    int xo = idx & 127;
    int yo = (idx >> 7) & 127;
    int c = (idx >> 14) & 511;
    int b = idx >> 23;
    int j = yo >> 1, i = xo >> 1;
    int y0, y1, x0, x1;
    float wy0, wy1, wx0, wx1;
    if (yo & 1) { y0 = j; y1 = min(j + 1, 63); wy0 = 0.75f; wy1 = 0.25f; }
    else        { y0 = max(j - 1, 0); y1 = j;  wy0 = 0.25f; wy1 = 0.75f; }
    if (xo & 1) { x0 = i; x1 = min(i + 1, 63); wx0 = 0.75f; wx1 = 0.25f; }
    else        { x0 = max(i - 1, 0); x1 = i;  wx0 = 0.25f; wx1 = 0.75f; }
    const float* p = x + (b * CIN1 + c) * (H0 * H0);
    float v = wy0 * (wx0 * p[y0 * H0 + x0] + wx1 * p[y0 * H0 + x1]) +
              wy1 * (wx0 * p[y1 * H0 + x0] + wx1 * p[y1 * H0 + x1]);
    g_xu[idx] = v * g_s1[b * CIN1 + c];
}

// ------------------------------ conv 3x3 -----------------------------------
// Block: 128 cout x 128 pixels (one image row). 256 threads, 8x8 acc/thread.
// cp.async double-buffered smem: input rows [BC][3][136] + weights [BC*9][128].
constexpr int TCO = 128;
constexpr int BC = 4;
constexpr int INSTRIDE = 136;
constexpr int INSZ = BC * 3 * INSTRIDE;   // 1632 floats
constexpr int WSZ = BC * 9 * TCO;         // 4608 floats
constexpr int BUFSZ = INSZ + WSZ;         // 6240 floats
constexpr int CONV_SMEM_BYTES = 2 * BUFSZ * 4;  // 49,920 B

__device__ __forceinline__ void cp_async16(float* dst, const float* src)
{
    unsigned da = (unsigned)__cvta_generic_to_shared(dst);
    asm volatile("cp.async.cg.shared.global [%0], [%1], 16;\n" ::"r"(da), "l"(src));
}

template <int CIN>
__global__ void __launch_bounds__(256)
conv3x3_kernel(const float* __restrict__ bias, float* __restrict__ outArg)
{
    const float* in = (CIN == 512) ? g_xu : g_h1;
    const float* wT = (CIN == 512) ? g_wT1 : g_wT2;
    const float* dsc = (CIN == 512) ? g_d1 : g_d2;
    const float* postScale = (CIN == 512) ? g_s2 : nullptr;  // fold s2 into conv1 epilogue
    float* out = (CIN == 512) ? g_h1 : outArg;

    extern __shared__ float smem[];
    const int t = threadIdx.x;
    const int b = blockIdx.z;
    const int coBase = blockIdx.y * TCO;
    const int y = blockIdx.x;
    const int tco = t >> 4;          // 0..15 -> 8 couts each
    const int px0 = (t & 15) * 8;    // 8 pixels each

    // permanent zero pad (img cols -1 and 128), both buffers
    if (t < 48) {
        int e = t;
        int bufi = e & 1; e >>= 1;
        int side = e & 1; e >>= 1;            // e: 0..11 = cil*3+r
        smem[bufi * BUFSZ + e * INSTRIDE + (side ? 132 : 3)] = 0.f;
    }

    const float* inB = in + (b * CIN) * NPIX;

    auto fill = [&](int buf, int chunk) {
        const int ciBase = chunk * BC;
        float* bin = smem + buf * BUFSZ;
        float* bwt = bin + INSZ;
        // input rows: BC*3 rows x 32 float4 (img cols 0..127 -> smem idx 4..131)
        for (int s = t; s < BC * 3 * 32; s += 256) {
            int cil = s / 96;
            int rem = s - cil * 96;
            int r = rem >> 5;
            int q = rem & 31;
            int yr = y - 1 + r;
            float* dst = bin + (cil * 3 + r) * INSTRIDE + 4 + q * 4;
            if ((unsigned)yr < (unsigned)HW) {
                const float* src = inB + ((ciBase + cil) * HW + yr) * HW + q * 4;
                cp_async16(dst, src);
            } else {
                *(float4*)dst = make_float4(0.f, 0.f, 0.f, 0.f);
            }
        }
        // weights: 36 rows x 32 float4 (fully coalesced from transposed layout)
        const float* wB = wT + (ciBase * 9) * CMID + coBase;
        for (int s = t; s < BC * 9 * 32; s += 256) {
            int row = s >> 5;
            int q = s & 31;
            cp_async16(bwt + row * TCO + q * 4, wB + row * CMID + q * 4);
        }
    };

    float acc[8][8];
#pragma unroll
    for (int i = 0; i < 8; i++)
#pragma unroll
        for (int j = 0; j < 8; j++) acc[i][j] = 0.f;

    constexpr int NCH = CIN / BC;
    fill(0, 0);
    asm volatile("cp.async.commit_group;\n");

    for (int c = 0; c < NCH; ++c) {
        const int cur = c & 1;
        if (c + 1 < NCH) {
            fill(cur ^ 1, c + 1);
            asm volatile("cp.async.commit_group;\n");
            asm volatile("cp.async.wait_group 1;\n");
        } else {
            asm volatile("cp.async.wait_group 0;\n");
        }
        __syncthreads();

        const float* bin = smem + cur * BUFSZ;
        const float* bwt = bin + INSZ;
#pragma unroll
        for (int cil = 0; cil < BC; cil++) {
#pragma unroll
            for (int r = 0; r < 3; r++) {
                const float* ip = bin + (cil * 3 + r) * INSTRIDE + px0 + 3;
                float4 xa = *(const float4*)(ip + 1);
                float4 xb = *(const float4*)(ip + 5);
                float x10[10] = {ip[0], xa.x, xa.y, xa.z, xa.w,
                                 xb.x, xb.y, xb.z, xb.w, ip[9]};
#pragma unroll
                for (int kc = 0; kc < 3; kc++) {
                    const float* wp = bwt + (cil * 9 + r * 3 + kc) * TCO + tco * 8;
                    float4 wa = *(const float4*)(wp);
                    float4 wb = *(const float4*)(wp + 4);
                    float w8[8] = {wa.x, wa.y, wa.z, wa.w, wb.x, wb.y, wb.z, wb.w};
#pragma unroll
                    for (int i = 0; i < 8; i++)
#pragma unroll
                        for (int j = 0; j < 8; j++)
                            acc[i][j] += w8[i] * x10[j + kc];
                }
            }
        }
        __syncthreads();
    }

    // epilogue: demod scale + bias + lrelu (+ optional post-scale for next conv)
#pragma unroll
    for (int i = 0; i < 8; i++) {
        int co = coBase + tco * 8 + i;
        float dv = dsc[b * CMID + co];
        float bv = bias[co];
        float ps = (postScale != nullptr) ? postScale[b * CMID + co] : 1.f;
        float o[8];
#pragma unroll
        for (int j = 0; j < 8; j++) {
            float v = acc[i][j] * dv + bv;
            v = v > 0.f ? v : LRELU * v;
            o[j] = v * ps;
        }
        float* op = out + ((b * CMID + co) * HW + y) * HW + px0;
        *(float4*)op = make_float4(o[0], o[1], o[2], o[3]);
        *(float4*)(op + 4) = make_float4(o[4], o[5], o[6], o[7]);
    }
}

// ------------------------------ to_rgb 1x1 ---------------------------------
__global__ void rgb_kernel(const float* __restrict__ h, const float* __restrict__ b3,
                           float* __restrict__ rgb)
{
    __shared__ float wm[3 * 256];
    const int b = blockIdx.y;
    const int t = threadIdx.x;
    const int p = blockIdx.x * 256 + t;
    wm[t] = g_wm3[b * 768 + t];
    wm[256 + t] = g_wm3[b * 768 + 256 + t];
    wm[512 + t] = g_wm3[b * 768 + 512 + t];
    __syncthreads();
    float a0 = b3[0], a1 = b3[1], a2 = b3[2];
    const float* hp = h + (b * CMID) * NPIX + p;
#pragma unroll 4
    for (int ci = 0; ci < CMID; ci++) {
        float v = hp[ci * NPIX];
        a0 += wm[ci] * v;
        a1 += wm[256 + ci] * v;
        a2 += wm[512 + ci] * v;
    }
    a0 = a0 > 0.f ? a0 : LRELU * a0;
    a1 = a1 > 0.f ? a1 : LRELU * a1;
    a2 = a2 > 0.f ? a2 : LRELU * a2;
    rgb[(b * 3 + 0) * NPIX + p] = a0;
    rgb[(b * 3 + 1) * NPIX + p] = a1;
    rgb[(b * 3 + 2) * NPIX + p] = a2;
}

// ------------------------------ launch -------------------------------------
extern "C" void kernel_launch(void* const* d_in, const int* in_sizes, int n_in,
                              void* d_out, int out_size)
{
    const float* x   = (const float*)d_in[0];
    const float* w   = (const float*)d_in[1];
    const float* w1  = (const float*)d_in[2];
    const float* b1  = (const float*)d_in[3];
    const float* a1w = (const float*)d_in[4];
    const float* a1b = (const float*)d_in[5];
    const float* w2  = (const float*)d_in[6];
    const float* b2  = (const float*)d_in[7];
    const float* a2w = (const float*)d_in[8];
    const float* a2b = (const float*)d_in[9];
    const float* w3  = (const float*)d_in[10];
    const float* b3  = (const float*)d_in[11];
    const float* a3w = (const float*)d_in[12];
    const float* a3b = (const float*)d_in[13];

    float* h_out = (float*)d_out;
    float* rgb_out = h_out + BATCH * CMID * NPIX;

    cudaFuncSetAttribute(conv3x3_kernel<512>, cudaFuncAttributeMaxDynamicSharedMemorySize,
                         CONV_SMEM_BYTES);
    cudaFuncSetAttribute(conv3x3_kernel<256>, cudaFuncAttributeMaxDynamicSharedMemorySize,
                         CONV_SMEM_BYTES);

    styles_kernel<<<BATCH, 512>>>(w, a1w, a1b, a2w, a2b, a3w, a3b, w3);
    demod_kernel<512><<<dim3(CMID, BATCH), 256>>>(w1);
    demod_kernel<256><<<dim3(CMID, BATCH), 256>>>(w2);
    wtrans_kernel<512><<<(CMID * 512 * 9) / 256, 256>>>(w1);
    wtrans_kernel<256><<<(CMID * 256 * 9) / 256, 256>>>(w2);
    upsample_kernel<<<(BATCH * CIN1 * NPIX) / 256, 256>>>(x);

    conv3x3_kernel<512><<<dim3(HW, CMID / TCO, BATCH), 256, CONV_SMEM_BYTES>>>(b1, nullptr);
    conv3x3_kernel<256><<<dim3(HW, CMID / TCO, BATCH), 256, CONV_SMEM_BYTES>>>(b2, h_out);

    rgb_kernel<<<dim3(NPIX / 256, BATCH), 256>>>(h_out, b3, rgb_out);
}

// round 3
// speedup vs baseline: 1.0017x; 1.0012x over previous
#include <cuda_runtime.h>

// ---------------------------------------------------------------------------
// StyleBlock: upsample2x(bilinear, half-pixel) -> modconv 512->256 3x3 (demod)
//             -> lrelu -> modconv 256->256 3x3 (demod) -> lrelu = h
//             -> 1x1 to_rgb (no demod) -> lrelu = rgb
// Key identity: modulation = per-(b,ci) input scale, demod = per-(b,co) output
// scale => convs use SHARED weights across batch (standard batched conv).
// ---------------------------------------------------------------------------

#define LRELU 0.2f
#define BATCH 4
#define CIN1 512
#define CMID 256
#define HW 128
#define NPIX (HW * HW)   // 16384
#define H0 64

// ------------------------------ scratch ------------------------------------
__device__ float g_xu[BATCH * CIN1 * NPIX];     // upsampled + s1-scaled input (134 MB)
__device__ float g_h1[BATCH * CMID * NPIX];     // conv1 output (pre-scaled by s2) (67 MB)
__device__ float g_wT1[CIN1 * 9 * CMID];        // w1 transposed to [(ci*9+k)][co]
__device__ float g_wT2[CMID * 9 * CMID];        // w2 transposed
__device__ float g_s1[BATCH * CIN1];
__device__ float g_s2[BATCH * CMID];
__device__ float g_s3[BATCH * CMID];
__device__ float g_d1[BATCH * CMID];
__device__ float g_d2[BATCH * CMID];
__device__ float g_wm3[BATCH * 3 * CMID];       // w3[co][ci]*s3[b][ci]

// ------------------------------ styles -------------------------------------
__global__ void styles_kernel(const float* __restrict__ w,
                              const float* __restrict__ a1w, const float* __restrict__ a1b,
                              const float* __restrict__ a2w, const float* __restrict__ a2b,
                              const float* __restrict__ a3w, const float* __restrict__ a3b,
                              const float* __restrict__ w3)
{
    __shared__ float wv[512];
    __shared__ float s3s[256];
    const int b = blockIdx.x;
    const int t = threadIdx.x;
    wv[t] = w[b * 512 + t];
    __syncthreads();
    {
        float acc = 0.f;
        const float* row = a1w + t * 512;
        for (int j = 0; j < 512; j++) acc += wv[j] * row[j];
        g_s1[b * CIN1 + t] = acc + a1b[t];
    }
    if (t < 256) {
        float acc = 0.f;
        const float* row = a2w + t * 512;
        for (int j = 0; j < 512; j++) acc += wv[j] * row[j];
        g_s2[b * CMID + t] = acc + a2b[t];
        acc = 0.f;
        row = a3w + t * 512;
        for (int j = 0; j < 512; j++) acc += wv[j] * row[j];
        float sv = acc + a3b[t];
        g_s3[b * CMID + t] = sv;
        s3s[t] = sv;
    }
    __syncthreads();
    if (t < 256) {
#pragma unroll
        for (int co = 0; co < 3; co++)
            g_wm3[(b * 3 + co) * CMID + t] = w3[co * CMID + t] * s3s[t];
    }
}

// -------------------------- demod factors ----------------------------------
// d[b,co] = rsqrt( sum_ci s[b,ci]^2 * sum_k w[co,ci,k]^2 + 1e-8 )
template <int CIN>
__global__ void demod_kernel(const float* __restrict__ w)
{
    const float* s = (CIN == 512) ? g_s1 : g_s2;
    float* d = (CIN == 512) ? g_d1 : g_d2;
    __shared__ float red[256];
    const int co = blockIdx.x;
    const int b = blockIdx.y;
    const int t = threadIdx.x;
    float tot = 0.f;
    for (int ci = t; ci < CIN; ci += 256) {
        const float* wp = w + (co * CIN + ci) * 9;
        float ws = 0.f;
#pragma unroll
        for (int k = 0; k < 9; k++) ws += wp[k] * wp[k];
        float sv = s[b * CIN + ci];
        tot += ws * sv * sv;
    }
    red[t] = tot;
    __syncthreads();
    for (int o = 128; o > 0; o >>= 1) {
        if (t < o) red[t] += red[t + o];
        __syncthreads();
    }
    if (t == 0) d[b * CMID + co] = rsqrtf(red[0] + 1e-8f);
}

// ------------------------- weight transpose --------------------------------
// wT[(ci*9+k)*256 + co] = w[co][ci][k]
template <int CIN>
__global__ void wtrans_kernel(const float* __restrict__ w)
{
    float* wT = (CIN == 512) ? g_wT1 : g_wT2;
    int idx = blockIdx.x * 256 + threadIdx.x;
    if (idx >= CMID * CIN * 9) return;
    int co = idx / (CIN * 9);
    int r = idx - co * (CIN * 9);
    int ci = r / 9;
    int k = r - ci * 9;
    wT[(ci * 9 + k) * CMID + co] = w[idx];
}

// -------------------- upsample (half-pixel bilinear) + s1 scale ------------
__global__ void upsample_kernel(const float* __restrict__ x)
{
    int idx = blockIdx.x * 256 + threadIdx.x;   // < 2^25
    int xo = idx & 127;
    int yo = (idx >> 7) & 127;
    int c = (idx >> 14) & 511;
    int b = idx >> 23;
    int j = yo >> 1, i = xo >> 1;
    int y0, y1, x0, x1;
    float wy0, wy1, wx0, wx1;
    if (yo & 1) { y0 = j; y1 = min(j + 1, 63); wy0 = 0.75f; wy1 = 0.25f; }
    else        { y0 = max(j - 1, 0); y1 = j;  wy0 = 0.25f; wy1 = 0.75f; }
    if (xo & 1) { x0 = i; x1 = min(i + 1, 63); wx0 = 0.75f; wx1 = 0.25f; }
    else        { x0 = max(i - 1, 0); x1 = i;  wx0 = 0.25f; wx1 = 0.75f; }
    const float* p = x + (b * CIN1 + c) * (H0 * H0);
    float v = wy0 * (wx0 * p[y0 * H0 + x0] + wx1 * p[y0 * H0 + x1]) +
              wy1 * (wx0 * p[y1 * H0 + x0] + wx1 * p[y1 * H0 + x1]);
    g_xu[idx] = v * g_s1[b * CIN1 + c];
}

// ------------------------------ conv 3x3 -----------------------------------
// Block: 128 cout x 128 pixels (one image row). 256 threads, 8x8 acc/thread.
// cp.async double-buffered smem: input rows [BC][3][136] + weights [BC*9][128].
constexpr int TCO = 128;
constexpr int BC = 4;
constexpr int INSTRIDE = 136;
constexpr int INSZ = BC * 3 * INSTRIDE;   // 1632 floats
constexpr int WSZ = BC * 9 * TCO;         // 4608 floats
constexpr int BUFSZ = INSZ + WSZ;         // 6240 floats
constexpr int CONV_SMEM_BYTES = 2 * BUFSZ * 4;  // 49,920 B

__device__ __forceinline__ void cp_async16(float* dst, const float* src)
{
    unsigned da = (unsigned)__cvta_generic_to_shared(dst);
    asm volatile("cp.async.cg.shared.global [%0], [%1], 16;\n" ::"r"(da), "l"(src));
}

template <int CIN>
__global__ void __launch_bounds__(256)
conv3x3_kernel(const float* __restrict__ bias, float* __restrict__ outArg)
{
    const float* in = (CIN == 512) ? g_xu : g_h1;
    const float* wT = (CIN == 512) ? g_wT1 : g_wT2;
    const float* dsc = (CIN == 512) ? g_d1 : g_d2;
    const float* postScale = (CIN == 512) ? g_s2 : nullptr;  // fold s2 into conv1 epilogue
    float* out = (CIN == 512) ? g_h1 : outArg;

    extern __shared__ float smem[];
    const int t = threadIdx.x;
    const int b = blockIdx.z;
    const int coBase = blockIdx.y * TCO;
    const int y = blockIdx.x;
    const int tco = t >> 4;          // 0..15 -> 8 couts each
    const int px0 = (t & 15) * 8;    // 8 pixels each

    // permanent zero pad (img cols -1 and 128), both buffers
    if (t < 48) {
        int e = t;
        int bufi = e & 1; e >>= 1;
        int side = e & 1; e >>= 1;            // e: 0..11 = cil*3+r
        smem[bufi * BUFSZ + e * INSTRIDE + (side ? 132 : 3)] = 0.f;
    }

    const float* inB = in + (b * CIN) * NPIX;

    auto fill = [&](int buf, int chunk) {
        const int ciBase = chunk * BC;
        float* bin = smem + buf * BUFSZ;
        float* bwt = bin + INSZ;
        // input rows: BC*3 rows x 32 float4 (img cols 0..127 -> smem idx 4..131)
        for (int s = t; s < BC * 3 * 32; s += 256) {
            int cil = s / 96;
            int rem = s - cil * 96;
            int r = rem >> 5;
            int q = rem & 31;
            int yr = y - 1 + r;
            float* dst = bin + (cil * 3 + r) * INSTRIDE + 4 + q * 4;
            if ((unsigned)yr < (unsigned)HW) {
                const float* src = inB + ((ciBase + cil) * HW + yr) * HW + q * 4;
                cp_async16(dst, src);
            } else {
                *(float4*)dst = make_float4(0.f, 0.f, 0.f, 0.f);
            }
        }
        // weights: 36 rows x 32 float4 (fully coalesced from transposed layout)
        const float* wB = wT + (ciBase * 9) * CMID + coBase;
        for (int s = t; s < BC * 9 * 32; s += 256) {
            int row = s >> 5;
            int q = s & 31;
            cp_async16(bwt + row * TCO + q * 4, wB + row * CMID + q * 4);
        }
    };

    float acc[8][8];
#pragma unroll
    for (int i = 0; i < 8; i++)
#pragma unroll
        for (int j = 0; j < 8; j++) acc[i][j] = 0.f;

    constexpr int NCH = CIN / BC;
    fill(0, 0);
    asm volatile("cp.async.commit_group;\n");

    for (int c = 0; c < NCH; ++c) {
        const int cur = c & 1;
        if (c + 1 < NCH) {
            fill(cur ^ 1, c + 1);
            asm volatile("cp.async.commit_group;\n");
            asm volatile("cp.async.wait_group 1;\n");
        } else {
            asm volatile("cp.async.wait_group 0;\n");
        }
        __syncthreads();

        const float* bin = smem + cur * BUFSZ;
        const float* bwt = bin + INSZ;
#pragma unroll
        for (int cil = 0; cil < BC; cil++) {
#pragma unroll
            for (int r = 0; r < 3; r++) {
                const float* ip = bin + (cil * 3 + r) * INSTRIDE + px0 + 3;
                float4 xa = *(const float4*)(ip + 1);
                float4 xb = *(const float4*)(ip + 5);
                float x10[10] = {ip[0], xa.x, xa.y, xa.z, xa.w,
                                 xb.x, xb.y, xb.z, xb.w, ip[9]};
#pragma unroll
                for (int kc = 0; kc < 3; kc++) {
                    const float* wp = bwt + (cil * 9 + r * 3 + kc) * TCO + tco * 8;
                    float4 wa = *(const float4*)(wp);
                    float4 wb = *(const float4*)(wp + 4);
                    float w8[8] = {wa.x, wa.y, wa.z, wa.w, wb.x, wb.y, wb.z, wb.w};
#pragma unroll
                    for (int i = 0; i < 8; i++)
#pragma unroll
                        for (int j = 0; j < 8; j++)
                            acc[i][j] += w8[i] * x10[j + kc];
                }
            }
        }
        __syncthreads();
    }

    // epilogue: demod scale + bias + lrelu (+ optional post-scale for next conv)
#pragma unroll
    for (int i = 0; i < 8; i++) {
        int co = coBase + tco * 8 + i;
        float dv = dsc[b * CMID + co];
        float bv = bias[co];
        float ps = (postScale != nullptr) ? postScale[b * CMID + co] : 1.f;
        float o[8];
#pragma unroll
        for (int j = 0; j < 8; j++) {
            float v = acc[i][j] * dv + bv;
            v = v > 0.f ? v : LRELU * v;
            o[j] = v * ps;
        }
        float* op = out + ((b * CMID + co) * HW + y) * HW + px0;
        *(float4*)op = make_float4(o[0], o[1], o[2], o[3]);
        *(float4*)(op + 4) = make_float4(o[4], o[5], o[6], o[7]);
    }
}

// ------------------------------ to_rgb 1x1 ---------------------------------
__global__ void rgb_kernel(const float* __restrict__ h, const float* __restrict__ b3,
                           float* __restrict__ rgb)
{
    __shared__ float wm[3 * 256];
    const int b = blockIdx.y;
    const int t = threadIdx.x;
    const int p = blockIdx.x * 256 + t;
    wm[t] = g_wm3[b * 768 + t];
    wm[256 + t] = g_wm3[b * 768 + 256 + t];
    wm[512 + t] = g_wm3[b * 768 + 512 + t];
    __syncthreads();
    float a0 = b3[0], a1 = b3[1], a2 = b3[2];
    const float* hp = h + (b * CMID) * NPIX + p;
#pragma unroll 4
    for (int ci = 0; ci < CMID; ci++) {
        float v = hp[ci * NPIX];
        a0 += wm[ci] * v;
        a1 += wm[256 + ci] * v;
        a2 += wm[512 + ci] * v;
    }
    a0 = a0 > 0.f ? a0 : LRELU * a0;
    a1 = a1 > 0.f ? a1 : LRELU * a1;
    a2 = a2 > 0.f ? a2 : LRELU * a2;
    rgb[(b * 3 + 0) * NPIX + p] = a0;
    rgb[(b * 3 + 1) * NPIX + p] = a1;
    rgb[(b * 3 + 2) * NPIX + p] = a2;
}

// ------------------------------ launch -------------------------------------
extern "C" void kernel_launch(void* const* d_in, const int* in_sizes, int n_in,
                              void* d_out, int out_size)
{
    const float* x   = (const float*)d_in[0];
    const float* w   = (const float*)d_in[1];
    const float* w1  = (const float*)d_in[2];
    const float* b1  = (const float*)d_in[3];
    const float* a1w = (const float*)d_in[4];
    const float* a1b = (const float*)d_in[5];
    const float* w2  = (const float*)d_in[6];
    const float* b2  = (const float*)d_in[7];
    const float* a2w = (const float*)d_in[8];
    const float* a2b = (const float*)d_in[9];
    const float* w3  = (const float*)d_in[10];
    const float* b3  = (const float*)d_in[11];
    const float* a3w = (const float*)d_in[12];
    const float* a3b = (const float*)d_in[13];

    float* h_out = (float*)d_out;
    float* rgb_out = h_out + BATCH * CMID * NPIX;

    cudaFuncSetAttribute(conv3x3_kernel<512>, cudaFuncAttributeMaxDynamicSharedMemorySize,
                         CONV_SMEM_BYTES);
    cudaFuncSetAttribute(conv3x3_kernel<256>, cudaFuncAttributeMaxDynamicSharedMemorySize,
                         CONV_SMEM_BYTES);

    styles_kernel<<<BATCH, 512>>>(w, a1w, a1b, a2w, a2b, a3w, a3b, w3);
    demod_kernel<512><<<dim3(CMID, BATCH), 256>>>(w1);
    demod_kernel<256><<<dim3(CMID, BATCH), 256>>>(w2);
    wtrans_kernel<512><<<(CMID * 512 * 9) / 256, 256>>>(w1);
    wtrans_kernel<256><<<(CMID * 256 * 9) / 256, 256>>>(w2);
    upsample_kernel<<<(BATCH * CIN1 * NPIX) / 256, 256>>>(x);

    conv3x3_kernel<512><<<dim3(HW, CMID / TCO, BATCH), 256, CONV_SMEM_BYTES>>>(b1, nullptr);
    conv3x3_kernel<256><<<dim3(HW, CMID / TCO, BATCH), 256, CONV_SMEM_BYTES>>>(b2, h_out);

    rgb_kernel<<<dim3(NPIX / 256, BATCH), 256>>>(h_out, b3, rgb_out);
}

// round 8
// speedup vs baseline: 4.0899x; 4.0830x over previous
#include <cuda_runtime.h>
#include <cuda_fp16.h>
#include <cstdint>

#define LRELU 0.2f
#define BATCH 4
#define CIN1 512
#define CMID 256
#define HW 128
#define NPIX (HW * HW)
#define H0 64
#define PW 130

// ------------------------------ scratch ------------------------------------
__device__ float g_xu[BATCH * CIN1 * NPIX];
__device__ __align__(16) __half g_xp[(size_t)BATCH * PW * PW * CIN1];
__device__ __align__(16) __half g_hp[(size_t)BATCH * PW * PW * CMID];
__device__ __align__(16) __half g_wp1[9 * 256 * CIN1];
__device__ __align__(16) __half g_wp2[9 * 256 * CMID];
__device__ float g_s1[BATCH * CIN1];
__device__ float g_s2[BATCH * CMID];
__device__ float g_d1[BATCH * CMID];
__device__ float g_d2[BATCH * CMID];
__device__ float g_wm3[BATCH * 3 * CMID];

// ------------------------------ helpers ------------------------------------
__device__ __forceinline__ uint32_t smem_u32(const void* p)
{
    uint32_t a;
    asm("{ .reg .u64 tmp; cvta.to.shared.u64 tmp, %1; cvt.u32.u64 %0, tmp; }"
        : "=r"(a) : "l"(p));
    return a;
}
#define SWZ(off) ((off) ^ (((off) >> 3) & 0x70))
__device__ __forceinline__ void cp16s(uint32_t dst, const void* src)
{
    asm volatile("cp.async.cg.shared.global [%0], [%1], 16;\n" ::"r"(dst), "l"(src));
}
#define CP_COMMIT() asm volatile("cp.async.commit_group;\n" ::: "memory")
#define CP_WAIT0()  asm volatile("cp.async.wait_group 0;\n" ::: "memory")
#define CP_WAIT1()  asm volatile("cp.async.wait_group 1;\n" ::: "memory")

__device__ __forceinline__ void ldsm4(uint32_t* r, uint32_t addr)
{
    asm volatile("ldmatrix.sync.aligned.m8n8.x4.shared.b16 {%0,%1,%2,%3}, [%4];"
                 : "=r"(r[0]), "=r"(r[1]), "=r"(r[2]), "=r"(r[3]) : "r"(addr));
}
__device__ __forceinline__ void mma168(float* d, const uint32_t* a, uint32_t b0, uint32_t b1)
{
    asm volatile(
        "mma.sync.aligned.m16n8k16.row.col.f32.f16.f16.f32 "
        "{%0,%1,%2,%3}, {%4,%5,%6,%7}, {%8,%9}, {%0,%1,%2,%3};"
        : "+f"(d[0]), "+f"(d[1]), "+f"(d[2]), "+f"(d[3])
        : "r"(a[0]), "r"(a[1]), "r"(a[2]), "r"(a[3]), "r"(b0), "r"(b1));
}

// ------------------------------ styles -------------------------------------
__global__ void styles_kernel(const float* __restrict__ w,
                              const float* __restrict__ a1w, const float* __restrict__ a1b,
                              const float* __restrict__ a2w, const float* __restrict__ a2b,
                              const float* __restrict__ a3w, const float* __restrict__ a3b,
                              const float* __restrict__ w3)
{
    __shared__ float wv[512];
    __shared__ float s3s[256];
    const int b = blockIdx.x;
    const int t = threadIdx.x;
    wv[t] = w[b * 512 + t];
    __syncthreads();
    {
        float acc = 0.f;
        const float* row = a1w + t * 512;
        for (int j = 0; j < 512; j++) acc += wv[j] * row[j];
        g_s1[b * CIN1 + t] = acc + a1b[t];
    }
    if (t < 256) {
        float acc = 0.f;
        const float* row = a2w + t * 512;
        for (int j = 0; j < 512; j++) acc += wv[j] * row[j];
        g_s2[b * CMID + t] = acc + a2b[t];
        acc = 0.f;
        row = a3w + t * 512;
        for (int j = 0; j < 512; j++) acc += wv[j] * row[j];
        s3s[t] = acc + a3b[t];
    }
    __syncthreads();
    if (t < 256) {
#pragma unroll
        for (int co = 0; co < 3; co++)
            g_wm3[(b * 3 + co) * CMID + t] = w3[co * CMID + t] * s3s[t];
    }
}

// -------------------------- demod factors ----------------------------------
template <int CIN>
__global__ void demod_kernel(const float* __restrict__ w)
{
    const float* s = (CIN == 512) ? g_s1 : g_s2;
    float* d = (CIN == 512) ? g_d1 : g_d2;
    __shared__ float red[256];
    const int co = blockIdx.x;
    const int b = blockIdx.y;
    const int t = threadIdx.x;
    float tot = 0.f;
    for (int ci = t; ci < CIN; ci += 256) {
        const float* wp = w + (co * CIN + ci) * 9;
        float ws = 0.f;
#pragma unroll
        for (int k = 0; k < 9; k++) ws += wp[k] * wp[k];
        float sv = s[b * CIN + ci];
        tot += ws * sv * sv;
    }
    red[t] = tot;
    __syncthreads();
    for (int o = 128; o > 0; o >>= 1) {
        if (t < o) red[t] += red[t + o];
        __syncthreads();
    }
    if (t == 0) d[b * CMID + co] = rsqrtf(red[0] + 1e-8f);
}

// ------------------- weight pack: wp[(k9*256+co)*CIN+ci] --------------------
template <int CIN>
__global__ void wpack_kernel(const float* __restrict__ w)
{
    __half* wp = (CIN == 512) ? g_wp1 : g_wp2;
    int idx = blockIdx.x * 256 + threadIdx.x;
    if (idx >= 256 * CIN * 9) return;
    int co = idx / (CIN * 9);
    int r = idx - co * (CIN * 9);
    int ci = r / 9;
    int k9 = r - ci * 9;
    wp[((size_t)(k9 * 256 + co)) * CIN + ci] = __float2half(w[idx]);
}

// -------------------- upsample (half-pixel bilinear) + s1 scale ------------
__global__ void upsample_kernel(const float* __restrict__ x)
{
    int idx = blockIdx.x * 256 + threadIdx.x;
    int xo = idx & 127;
    int yo = (idx >> 7) & 127;
    int c = (idx >> 14) & 511;
    int b = idx >> 23;
    int j = yo >> 1, i = xo >> 1;
    int y0, y1, x0, x1;
    float wy0, wy1, wx0, wx1;
    if (yo & 1) { y0 = j; y1 = min(j + 1, 63); wy0 = 0.75f; wy1 = 0.25f; }
    else        { y0 = max(j - 1, 0); y1 = j;  wy0 = 0.25f; wy1 = 0.75f; }
    if (xo & 1) { x0 = i; x1 = min(i + 1, 63); wx0 = 0.75f; wx1 = 0.25f; }
    else        { x0 = max(i - 1, 0); x1 = i;  wx0 = 0.25f; wx1 = 0.75f; }
    const float* p = x + (b * CIN1 + c) * (H0 * H0);
    float v = wy0 * (wx0 * p[y0 * H0 + x0] + wx1 * p[y0 * H0 + x1]) +
              wy1 * (wx0 * p[y1 * H0 + x0] + wx1 * p[y1 * H0 + x1]);
    g_xu[idx] = v * g_s1[b * CIN1 + c];
}

// --------- transpose-pack NCHW fp32 -> padded NHWC fp16 image ---------------
__global__ void packx_kernel()
{
    __shared__ float tile[32 * 129];
    const int y = blockIdx.x;
    const int cg = blockIdx.y;
    const int b = blockIdx.z;
    const int t = threadIdx.x;
    const float* src = g_xu + ((size_t)(b * CIN1 + cg * 32)) * NPIX + (size_t)y * HW;
#pragma unroll
    for (int o = 0; o < 16; o++) {
        int idx = t + o * 256;
        int r = idx >> 7, c = idx & 127;
        tile[r * 129 + c] = src[(size_t)r * NPIX + c];
    }
    __syncthreads();
    int px = t >> 1, half = t & 1;
    __half* dst = g_xp + ((size_t)((b * PW) + (y + 1)) * PW + (px + 1)) * CIN1
                  + cg * 32 + half * 16;
#pragma unroll
    for (int k = 0; k < 16; k++)
        dst[k] = __float2half(tile[(half * 16 + k) * 129 + px]);
}

// ----------------------- zero padded borders (xp + hp) ---------------------
__global__ void zborder_kernel()
{
    int i = blockIdx.x * 256 + threadIdx.x;
    const int NXP = 4 * 516 * 64;   // int4 units (1024B/pixel)
    const int NHP = 4 * 516 * 32;   // (512B/pixel)
    if (i >= NXP + NHP) return;
    bool isx = i < NXP;
    int u = isx ? i : i - NXP;
    int per = isx ? 64 : 32;
    int q = u % per;
    int e = u / per;
    int b = e / 516; e -= b * 516;
    int py, px;
    if (e < 130)      { py = 0;   px = e; }
    else if (e < 260) { py = 129; px = e - 130; }
    else if (e < 388) { px = 0;   py = e - 259; }
    else              { px = 129; py = e - 387; }
    size_t pix = (size_t)(b * PW + py) * PW + px;
    int4 z = make_int4(0, 0, 0, 0);
    if (isx) ((int4*)g_xp)[pix * 64 + q] = z;
    else     ((int4*)g_hp)[pix * 32 + q] = z;
}

// --------------------------- conv via mma.sync ------------------------------
// CTA: 128 cout x 128 pixels (one row), BK=64, 3-stage cp.async ring.
// 8 warps: 2 (M) x 4 (N); warp tile 64x32 = 4x4 m16n8k16 frags.
constexpr int STAGE = 32768;            // A 16KB + B 16KB
constexpr int CONV_SMEM = 3 * STAGE + 1024;

template <int CIN, bool FIRST>
__global__ void __launch_bounds__(256)
conv_mma_kernel(const float* __restrict__ bias, float* __restrict__ hOut)
{
    constexpr int NI = 9 * CIN / 64;
    const __half* xp = FIRST ? g_xp : g_hp;
    const __half* wp = FIRST ? g_wp1 : g_wp2;
    const float* dsc = FIRST ? g_d1 : g_d2;

    extern __shared__ char dsm[];
    char* basep = (char*)(((uintptr_t)dsm + 1023) & ~(uintptr_t)1023);
    const uint32_t base = smem_u32(basep);
    __shared__ float sd[256], sbv[256], ssv[256];

    const int t = threadIdx.x;
    const int wid = t >> 5;
    const int lane = t & 31;
    const int nb = blockIdx.x;
    const int b = nb >> 7;
    const int y = nb & 127;
    const int co0 = blockIdx.y * 128;
    const int warpM = wid >> 2, warpN = wid & 3;

    sd[t] = dsc[b * 256 + t];
    sbv[t] = bias[t];
    ssv[t] = FIRST ? g_s2[b * 256 + t] : 1.f;

    const char* xpB = (const char*)(xp + (size_t)b * PW * PW * CIN);
    const char* wpB = (const char*)wp;

    auto fill = [&](int s, int kk) {
        int k9 = kk / CIN, kc = kk - k9 * CIN;
        int dy = k9 / 3, dx = k9 - (k9 / 3) * 3;
        uint32_t ab = base + s * STAGE;
#pragma unroll
        for (int u = t; u < 2048; u += 256) {
            int tile = u >> 10;
            int row = (u >> 3) & 127;
            int q = u & 7;
            uint32_t dst = ab + tile * 16384 + SWZ(row * 128 + q * 16);
            const char* src;
            if (tile == 0) {   // A = weights [co][k]
                src = wpB + ((size_t)(k9 * 256 + co0 + row) * CIN + kc) * 2 + q * 16;
            } else {           // B = pixels [px][k]
                src = xpB + ((size_t)((y + dy) * PW + (row + dx)) * CIN + kc) * 2 + q * 16;
            }
            cp16s(dst, src);
        }
    };

    float acc[4][4][4];
#pragma unroll
    for (int mt = 0; mt < 4; mt++)
#pragma unroll
        for (int nt = 0; nt < 4; nt++)
#pragma unroll
            for (int r = 0; r < 4; r++) acc[mt][nt][r] = 0.f;

    fill(0, 0); CP_COMMIT();
    fill(1, 64); CP_COMMIT();

    for (int i = 0; i < NI; i++) {
        if (i == NI - 1) CP_WAIT0(); else CP_WAIT1();
        __syncthreads();
        if (i + 2 < NI) { fill((i + 2) % 3, (i + 2) * 64); CP_COMMIT(); }

        uint32_t aB = base + (i % 3) * STAGE;
        uint32_t bB = aB + 16384;
#pragma unroll
        for (int ks = 0; ks < 4; ks++) {
            int colb = ks * 32 + (lane >> 4) * 16;
            uint32_t a[4][4];
#pragma unroll
            for (int mt = 0; mt < 4; mt++) {
                int row = warpM * 64 + mt * 16 + (lane & 15);
                ldsm4(a[mt], aB + SWZ(row * 128 + colb));
            }
            uint32_t bf[2][4];
#pragma unroll
            for (int g = 0; g < 2; g++) {
                int row = warpN * 32 + g * 16 + (lane & 15);
                ldsm4(bf[g], bB + SWZ(row * 128 + colb));   // non-trans: [px][k], pairs along k
            }
#pragma unroll
            for (int mt = 0; mt < 4; mt++)
#pragma unroll
                for (int nt = 0; nt < 4; nt++)
                    mma168(acc[mt][nt], a[mt], bf[nt >> 1][nt & 1], bf[nt >> 1][(nt & 1) + 2]);
        }
    }
    __syncthreads();

    const int lr = lane >> 2;
    const int lc = lane & 3;
    if (FIRST) {
        // epilogue -> smem [px][136 co] fp16 -> coalesced g_hp
        __half* esm = (__half*)basep;
#pragma unroll
        for (int mt = 0; mt < 4; mt++) {
#pragma unroll
            for (int nt = 0; nt < 4; nt++) {
#pragma unroll
                for (int half = 0; half < 2; half++) {
                    int col = warpM * 64 + mt * 16 + lr + half * 8;   // local co
                    int co = co0 + col;
                    float d0 = acc[mt][nt][half * 2 + 0];
                    float d1 = acc[mt][nt][half * 2 + 1];
                    float v0 = d0 * sd[co] + sbv[co];
                    float v1 = d1 * sd[co] + sbv[co];
                    v0 = (v0 > 0.f ? v0 : LRELU * v0) * ssv[co];
                    v1 = (v1 > 0.f ? v1 : LRELU * v1) * ssv[co];
                    int px = warpN * 32 + nt * 8 + lc * 2;
                    esm[px * 136 + col] = __float2half(v0);
                    esm[(px + 1) * 136 + col] = __float2half(v1);
                }
            }
        }
        __syncthreads();
        // copy out: row px (128), 128 couts = 256B -> 16 chunks of 16B
        int pr = t >> 1, part = t & 1;
        const char* srow = (const char*)esm + pr * 272 + part * 128;
        __half* drow = g_hp + ((size_t)(b * PW + (y + 1)) * PW + (pr + 1)) * CMID
                       + co0 + part * 64;
#pragma unroll
        for (int c = 0; c < 8; c++)
            *(int4*)((char*)drow + c * 16) = *(const int4*)(srow + c * 16);
    } else {
#pragma unroll
        for (int mt = 0; mt < 4; mt++) {
#pragma unroll
            for (int nt = 0; nt < 4; nt++) {
#pragma unroll
                for (int half = 0; half < 2; half++) {
                    int co = co0 + warpM * 64 + mt * 16 + lr + half * 8;
                    float d0 = acc[mt][nt][half * 2 + 0];
                    float d1 = acc[mt][nt][half * 2 + 1];
                    float v0 = d0 * sd[co] + sbv[co];
                    float v1 = d1 * sd[co] + sbv[co];
                    v0 = v0 > 0.f ? v0 : LRELU * v0;
                    v1 = v1 > 0.f ? v1 : LRELU * v1;
                    int px = warpN * 32 + nt * 8 + lc * 2;
                    float2 o = make_float2(v0, v1);
                    *(float2*)(hOut + ((size_t)(b * 256 + co)) * NPIX + y * HW + px) = o;
                }
            }
        }
    }
}

// ------------------------------ to_rgb 1x1 ---------------------------------
__global__ void rgb_kernel(const float* __restrict__ h, const float* __restrict__ b3,
                           float* __restrict__ rgb)
{
    __shared__ float wm[3 * 256];
    const int b = blockIdx.y;
    const int t = threadIdx.x;
    const int p = blockIdx.x * 256 + t;
    wm[t] = g_wm3[b * 768 + t];
    wm[256 + t] = g_wm3[b * 768 + 256 + t];
    wm[512 + t] = g_wm3[b * 768 + 512 + t];
    __syncthreads();
    float a0 = b3[0], a1 = b3[1], a2 = b3[2];
    const float* hp = h + (size_t)(b * CMID) * NPIX + p;
#pragma unroll 4
    for (int ci = 0; ci < CMID; ci++) {
        float v = hp[(size_t)ci * NPIX];
        a0 += wm[ci] * v;
        a1 += wm[256 + ci] * v;
        a2 += wm[512 + ci] * v;
    }
    a0 = a0 > 0.f ? a0 : LRELU * a0;
    a1 = a1 > 0.f ? a1 : LRELU * a1;
    a2 = a2 > 0.f ? a2 : LRELU * a2;
    rgb[(b * 3 + 0) * NPIX + p] = a0;
    rgb[(b * 3 + 1) * NPIX + p] = a1;
    rgb[(b * 3 + 2) * NPIX + p] = a2;
}

// ------------------------------ launch -------------------------------------
extern "C" void kernel_launch(void* const* d_in, const int* in_sizes, int n_in,
                              void* d_out, int out_size)
{
    const float* x   = (const float*)d_in[0];
    const float* w   = (const float*)d_in[1];
    const float* w1  = (const float*)d_in[2];
    const float* b1  = (const float*)d_in[3];
    const float* a1w = (const float*)d_in[4];
    const float* a1b = (const float*)d_in[5];
    const float* w2  = (const float*)d_in[6];
    const float* b2  = (const float*)d_in[7];
    const float* a2w = (const float*)d_in[8];
    const float* a2b = (const float*)d_in[9];
    const float* w3  = (const float*)d_in[10];
    const float* b3  = (const float*)d_in[11];
    const float* a3w = (const float*)d_in[12];
    const float* a3b = (const float*)d_in[13];

    float* h_out = (float*)d_out;
    float* rgb_out = h_out + BATCH * CMID * NPIX;

    cudaFuncSetAttribute(conv_mma_kernel<512, true>,
                         cudaFuncAttributeMaxDynamicSharedMemorySize, CONV_SMEM);
    cudaFuncSetAttribute(conv_mma_kernel<256, false>,
                         cudaFuncAttributeMaxDynamicSharedMemorySize, CONV_SMEM);

    styles_kernel<<<BATCH, 512>>>(w, a1w, a1b, a2w, a2b, a3w, a3b, w3);
    demod_kernel<512><<<dim3(CMID, BATCH), 256>>>(w1);
    demod_kernel<256><<<dim3(CMID, BATCH), 256>>>(w2);
    wpack_kernel<512><<<(256 * 512 * 9 + 255) / 256, 256>>>(w1);
    wpack_kernel<256><<<(256 * 256 * 9 + 255) / 256, 256>>>(w2);
    upsample_kernel<<<(BATCH * CIN1 * NPIX) / 256, 256>>>(x);
    packx_kernel<<<dim3(HW, 16, BATCH), 256>>>();
    zborder_kernel<<<(4 * 516 * 96 + 255) / 256, 256>>>();

    conv_mma_kernel<512, true><<<dim3(512, 2), 256, CONV_SMEM>>>(b1, nullptr);
    conv_mma_kernel<256, false><<<dim3(512, 2), 256, CONV_SMEM>>>(b2, h_out);

    rgb_kernel<<<dim3(NPIX / 256, BATCH), 256>>>(h_out, b3, rgb_out);
}

// round 9
// speedup vs baseline: 4.2192x; 1.0316x over previous
#include <cuda_runtime.h>
#include <cuda_fp16.h>
#include <cstdint>

#define LRELU 0.2f
#define BATCH 4
#define CIN1 512
#define CMID 256
#define HW 128
#define NPIX (HW * HW)
#define H0 64
#define PW 130

// ------------------------------ scratch ------------------------------------
__device__ __align__(16) __half g_xp[(size_t)BATCH * PW * PW * CIN1];
__device__ __align__(16) __half g_hp[(size_t)BATCH * PW * PW * CMID];
__device__ __align__(16) __half g_wp1[9 * 256 * CIN1];
__device__ __align__(16) __half g_wp2[9 * 256 * CMID];
__device__ float g_s1[BATCH * CIN1];
__device__ float g_s2[BATCH * CMID];
__device__ float g_d1[BATCH * CMID];
__device__ float g_d2[BATCH * CMID];
__device__ float g_wm3[BATCH * 3 * CMID];

// ------------------------------ helpers ------------------------------------
__device__ __forceinline__ uint32_t smem_u32(const void* p)
{
    uint32_t a;
    asm("{ .reg .u64 tmp; cvta.to.shared.u64 tmp, %1; cvt.u32.u64 %0, tmp; }"
        : "=r"(a) : "l"(p));
    return a;
}
#define SWZ(off) ((off) ^ (((off) >> 3) & 0x70))
__device__ __forceinline__ void cp16s(uint32_t dst, const void* src)
{
    asm volatile("cp.async.cg.shared.global [%0], [%1], 16;\n" ::"r"(dst), "l"(src));
}
#define CP_COMMIT() asm volatile("cp.async.commit_group;\n" ::: "memory")
#define CP_WAIT0()  asm volatile("cp.async.wait_group 0;\n" ::: "memory")
#define CP_WAIT1()  asm volatile("cp.async.wait_group 1;\n" ::: "memory")

__device__ __forceinline__ void ldsm4(uint32_t* r, uint32_t addr)
{
    asm volatile("ldmatrix.sync.aligned.m8n8.x4.shared.b16 {%0,%1,%2,%3}, [%4];"
                 : "=r"(r[0]), "=r"(r[1]), "=r"(r[2]), "=r"(r[3]) : "r"(addr));
}
__device__ __forceinline__ void mma168(float* d, const uint32_t* a, uint32_t b0, uint32_t b1)
{
    asm volatile(
        "mma.sync.aligned.m16n8k16.row.col.f32.f16.f16.f32 "
        "{%0,%1,%2,%3}, {%4,%5,%6,%7}, {%8,%9}, {%0,%1,%2,%3};"
        : "+f"(d[0]), "+f"(d[1]), "+f"(d[2]), "+f"(d[3])
        : "r"(a[0]), "r"(a[1]), "r"(a[2]), "r"(a[3]), "r"(b0), "r"(b1));
}

// ------------------------------ styles -------------------------------------
__global__ void styles_kernel(const float* __restrict__ w,
                              const float* __restrict__ a1w, const float* __restrict__ a1b,
                              const float* __restrict__ a2w, const float* __restrict__ a2b,
                              const float* __restrict__ a3w, const float* __restrict__ a3b,
                              const float* __restrict__ w3)
{
    __shared__ float wv[512];
    __shared__ float s3s[256];
    const int b = blockIdx.x;
    const int t = threadIdx.x;
    wv[t] = w[b * 512 + t];
    __syncthreads();
    {
        float acc = 0.f;
        const float* row = a1w + t * 512;
        for (int j = 0; j < 512; j++) acc += wv[j] * row[j];
        g_s1[b * CIN1 + t] = acc + a1b[t];
    }
    if (t < 256) {
        float acc = 0.f;
        const float* row = a2w + t * 512;
        for (int j = 0; j < 512; j++) acc += wv[j] * row[j];
        g_s2[b * CMID + t] = acc + a2b[t];
        acc = 0.f;
        row = a3w + t * 512;
        for (int j = 0; j < 512; j++) acc += wv[j] * row[j];
        s3s[t] = acc + a3b[t];
    }
    __syncthreads();
    if (t < 256) {
#pragma unroll
        for (int co = 0; co < 3; co++)
            g_wm3[(b * 3 + co) * CMID + t] = w3[co * CMID + t] * s3s[t];
    }
}

// -------------------------- demod factors ----------------------------------
template <int CIN>
__global__ void demod_kernel(const float* __restrict__ w)
{
    const float* s = (CIN == 512) ? g_s1 : g_s2;
    float* d = (CIN == 512) ? g_d1 : g_d2;
    __shared__ float red[256];
    const int co = blockIdx.x;
    const int b = blockIdx.y;
    const int t = threadIdx.x;
    float tot = 0.f;
    for (int ci = t; ci < CIN; ci += 256) {
        const float* wp = w + (co * CIN + ci) * 9;
        float ws = 0.f;
#pragma unroll
        for (int k = 0; k < 9; k++) ws += wp[k] * wp[k];
        float sv = s[b * CIN + ci];
        tot += ws * sv * sv;
    }
    red[t] = tot;
    __syncthreads();
    for (int o = 128; o > 0; o >>= 1) {
        if (t < o) red[t] += red[t + o];
        __syncthreads();
    }
    if (t == 0) d[b * CMID + co] = rsqrtf(red[0] + 1e-8f);
}

// ------------------- weight pack: wp[(k9*256+co)*CIN+ci] --------------------
template <int CIN>
__global__ void wpack_kernel(const float* __restrict__ w)
{
    __half* wp = (CIN == 512) ? g_wp1 : g_wp2;
    int idx = blockIdx.x * 256 + threadIdx.x;
    if (idx >= 256 * CIN * 9) return;
    int co = idx / (CIN * 9);
    int r = idx - co * (CIN * 9);
    int ci = r / 9;
    int k9 = r - ci * 9;
    wp[((size_t)(k9 * 256 + co)) * CIN + ci] = __float2half(w[idx]);
}

// --- fused: upsample (half-pixel bilinear) + s1 scale + NHWC fp16 pack ------
// block: (y 0..127, cg 0..15, b 0..3), 256 threads. smem: 32ch x 2rows x 64col.
__global__ void __launch_bounds__(256) uppack_kernel(const float* __restrict__ x)
{
    __shared__ float sm[32][2][64];
    __shared__ float s1s[32];
    const int y = blockIdx.x;
    const int cg = blockIdx.y;
    const int b = blockIdx.z;
    const int t = threadIdx.x;

    int j = y >> 1;
    int y0, y1;
    float wy0, wy1;
    if (y & 1) { y0 = j; y1 = min(j + 1, 63); wy0 = 0.75f; wy1 = 0.25f; }
    else       { y0 = max(j - 1, 0); y1 = j;  wy0 = 0.25f; wy1 = 0.75f; }

    if (t < 32) s1s[t] = g_s1[b * CIN1 + cg * 32 + t];
#pragma unroll
    for (int o = 0; o < 16; o++) {
        int idx = t + o * 256;
        int rr = idx >> 6;        // 0..63 = ch*2 + r
        int col = idx & 63;
        int ch = rr >> 1, r = rr & 1;
        sm[ch][r][col] = x[((size_t)(b * CIN1 + cg * 32 + ch) * H0 + (r ? y1 : y0)) * H0 + col];
    }
    __syncthreads();

    const int px = t >> 1, half = t & 1;
    int i = px >> 1;
    int x0, x1;
    float wx0, wx1;
    if (px & 1) { x0 = i; x1 = min(i + 1, 63); wx0 = 0.75f; wx1 = 0.25f; }
    else        { x0 = max(i - 1, 0); x1 = i;  wx0 = 0.25f; wx1 = 0.75f; }

    __half* dst = g_xp + ((size_t)((b * PW) + (y + 1)) * PW + (px + 1)) * CIN1
                  + cg * 32 + half * 16;
#pragma unroll
    for (int k = 0; k < 16; k++) {
        int ch = half * 16 + k;
        float v = wy0 * (wx0 * sm[ch][0][x0] + wx1 * sm[ch][0][x1]) +
                  wy1 * (wx0 * sm[ch][1][x0] + wx1 * sm[ch][1][x1]);
        dst[k] = __float2half(v * s1s[ch]);
    }
}

// ----------------------- zero padded borders (xp + hp) ---------------------
__global__ void zborder_kernel()
{
    int i = blockIdx.x * 256 + threadIdx.x;
    const int NXP = 4 * 516 * 64;   // int4 units (1024B/pixel)
    const int NHP = 4 * 516 * 32;   // (512B/pixel)
    if (i >= NXP + NHP) return;
    bool isx = i < NXP;
    int u = isx ? i : i - NXP;
    int per = isx ? 64 : 32;
    int q = u % per;
    int e = u / per;
    int b = e / 516; e -= b * 516;
    int py, px;
    if (e < 130)      { py = 0;   px = e; }
    else if (e < 260) { py = 129; px = e - 130; }
    else if (e < 388) { px = 0;   py = e - 259; }
    else              { px = 129; py = e - 387; }
    size_t pix = (size_t)(b * PW + py) * PW + px;
    int4 z = make_int4(0, 0, 0, 0);
    if (isx) ((int4*)g_xp)[pix * 64 + q] = z;
    else     ((int4*)g_hp)[pix * 32 + q] = z;
}

// --------------------------- conv via mma.sync ------------------------------
// CTA: 256 cout x 128 pixels (one row), BK=64, 3-stage cp.async ring, 512 thr.
// 16 warps: 4 (M couts) x 4 (N pixels); warp tile 64x32 = 4x4 m16n8k16 frags.
constexpr int STAGE = 49152;            // A 32KB + B 16KB
constexpr int CONV_SMEM = 3 * STAGE + 1024;

template <int CIN, bool FIRST>
__global__ void __launch_bounds__(512)
conv_mma_kernel(const float* __restrict__ bias, float* __restrict__ hOut)
{
    constexpr int NI = 9 * CIN / 64;
    const __half* xp = FIRST ? g_xp : g_hp;
    const __half* wp = FIRST ? g_wp1 : g_wp2;
    const float* dsc = FIRST ? g_d1 : g_d2;

    extern __shared__ char dsm[];
    char* basep = (char*)(((uintptr_t)dsm + 1023) & ~(uintptr_t)1023);
    const uint32_t base = smem_u32(basep);
    __shared__ float sd[256], sbv[256], ssv[256];

    const int t = threadIdx.x;
    const int wid = t >> 5;
    const int lane = t & 31;
    const int nb = blockIdx.x;
    const int b = nb >> 7;
    const int y = nb & 127;
    const int warpM = wid >> 2, warpN = wid & 3;

    if (t < 256) {
        sd[t] = dsc[b * 256 + t];
        sbv[t] = bias[t];
        ssv[t] = FIRST ? g_s2[b * 256 + t] : 1.f;
    }

    const char* xpB = (const char*)(xp + (size_t)b * PW * PW * CIN);
    const char* wpB = (const char*)wp;

    auto fill = [&](int s, int kk) {
        int k9 = kk / CIN, kc = kk - k9 * CIN;
        int dy = k9 / 3, dx = k9 - (k9 / 3) * 3;
        uint32_t ab = base + s * STAGE;
#pragma unroll
        for (int u = t; u < 3072; u += 512) {
            const char* src;
            uint32_t dst;
            if (u < 2048) {        // A = weights [co 0..255][k]
                int row = u >> 3, q = u & 7;
                dst = ab + SWZ(row * 128 + q * 16);
                src = wpB + ((size_t)(k9 * 256 + row) * CIN + kc) * 2 + q * 16;
            } else {               // B = pixels [px 0..127][k]
                int v = u - 2048;
                int row = v >> 3, q = v & 7;
                dst = ab + 32768 + SWZ(row * 128 + q * 16);
                src = xpB + ((size_t)((y + dy) * PW + (row + dx)) * CIN + kc) * 2 + q * 16;
            }
            cp16s(dst, src);
        }
    };

    float acc[4][4][4];
#pragma unroll
    for (int mt = 0; mt < 4; mt++)
#pragma unroll
        for (int nt = 0; nt < 4; nt++)
#pragma unroll
            for (int r = 0; r < 4; r++) acc[mt][nt][r] = 0.f;

    fill(0, 0); CP_COMMIT();
    fill(1, 64); CP_COMMIT();

    for (int i = 0; i < NI; i++) {
        if (i == NI - 1) CP_WAIT0(); else CP_WAIT1();
        __syncthreads();
        if (i + 2 < NI) { fill((i + 2) % 3, (i + 2) * 64); CP_COMMIT(); }

        uint32_t aB = base + (i % 3) * STAGE;
        uint32_t bB = aB + 32768;
#pragma unroll
        for (int ks = 0; ks < 4; ks++) {
            int colb = ks * 32 + (lane >> 4) * 16;
            uint32_t a[4][4];
#pragma unroll
            for (int mt = 0; mt < 4; mt++) {
                int row = warpM * 64 + mt * 16 + (lane & 15);
                ldsm4(a[mt], aB + SWZ(row * 128 + colb));
            }
            uint32_t bf[2][4];
#pragma unroll
            for (int g = 0; g < 2; g++) {
                int row = warpN * 32 + g * 16 + (lane & 15);
                ldsm4(bf[g], bB + SWZ(row * 128 + colb));   // [px][k]: pairs along k
            }
#pragma unroll
            for (int mt = 0; mt < 4; mt++)
#pragma unroll
                for (int nt = 0; nt < 4; nt++)
                    mma168(acc[mt][nt], a[mt], bf[nt >> 1][nt & 1], bf[nt >> 1][(nt & 1) + 2]);
        }
    }
    __syncthreads();

    const int lr = lane >> 2;
    const int lc = lane & 3;
    if (FIRST) {
        // epilogue -> smem [px 128][co 256 + 8 pad] fp16 -> coalesced g_hp
        __half* esm = (__half*)basep;
#pragma unroll
        for (int mt = 0; mt < 4; mt++) {
#pragma unroll
            for (int nt = 0; nt < 4; nt++) {
#pragma unroll
                for (int half = 0; half < 2; half++) {
                    int co = warpM * 64 + mt * 16 + lr + half * 8;
                    float d0 = acc[mt][nt][half * 2 + 0];
                    float d1 = acc[mt][nt][half * 2 + 1];
                    float v0 = d0 * sd[co] + sbv[co];
                    float v1 = d1 * sd[co] + sbv[co];
                    v0 = (v0 > 0.f ? v0 : LRELU * v0) * ssv[co];
                    v1 = (v1 > 0.f ? v1 : LRELU * v1) * ssv[co];
                    int px = warpN * 32 + nt * 8 + lc * 2;
                    esm[px * 264 + co] = __float2half(v0);
                    esm[(px + 1) * 264 + co] = __float2half(v1);
                }
            }
        }
        __syncthreads();
        // copy out: 128 px rows x 256 couts (512B); thread = (px, quarter)
        int pr = t >> 2, part = t & 3;
        const char* srow = (const char*)esm + pr * 528 + part * 128;
        __half* drow = g_hp + ((size_t)(b * PW + (y + 1)) * PW + (pr + 1)) * CMID
                       + part * 64;
#pragma unroll
        for (int c = 0; c < 8; c++)
            *(int4*)((char*)drow + c * 16) = *(const int4*)(srow + c * 16);
    } else {
#pragma unroll
        for (int mt = 0; mt < 4; mt++) {
#pragma unroll
            for (int nt = 0; nt < 4; nt++) {
#pragma unroll
                for (int half = 0; half < 2; half++) {
                    int co = warpM * 64 + mt * 16 + lr + half * 8;
                    float d0 = acc[mt][nt][half * 2 + 0];
                    float d1 = acc[mt][nt][half * 2 + 1];
                    float v0 = d0 * sd[co] + sbv[co];
                    float v1 = d1 * sd[co] + sbv[co];
                    v0 = v0 > 0.f ? v0 : LRELU * v0;
                    v1 = v1 > 0.f ? v1 : LRELU * v1;
                    int px = warpN * 32 + nt * 8 + lc * 2;
                    float2 o = make_float2(v0, v1);
                    *(float2*)(hOut + ((size_t)(b * 256 + co)) * NPIX + y * HW + px) = o;
                }
            }
        }
    }
}

// ------------------------------ to_rgb 1x1 ---------------------------------
__global__ void rgb_kernel(const float* __restrict__ h, const float* __restrict__ b3,
                           float* __restrict__ rgb)
{
    __shared__ float wm[3 * 256];
    const int b = blockIdx.y;
    const int t = threadIdx.x;
    const int p = blockIdx.x * 256 + t;
    wm[t] = g_wm3[b * 768 + t];
    wm[256 + t] = g_wm3[b * 768 + 256 + t];
    wm[512 + t] = g_wm3[b * 768 + 512 + t];
    __syncthreads();
    float a0 = b3[0], a1 = b3[1], a2 = b3[2];
    const float* hp = h + (size_t)(b * CMID) * NPIX + p;
#pragma unroll 4
    for (int ci = 0; ci < CMID; ci++) {
        float v = hp[(size_t)ci * NPIX];
        a0 += wm[ci] * v;
        a1 += wm[256 + ci] * v;
        a2 += wm[512 + ci] * v;
    }
    a0 = a0 > 0.f ? a0 : LRELU * a0;
    a1 = a1 > 0.f ? a1 : LRELU * a1;
    a2 = a2 > 0.f ? a2 : LRELU * a2;
    rgb[(b * 3 + 0) * NPIX + p] = a0;
    rgb[(b * 3 + 1) * NPIX + p] = a1;
    rgb[(b * 3 + 2) * NPIX + p] = a2;
}

// ------------------------------ launch -------------------------------------
extern "C" void kernel_launch(void* const* d_in, const int* in_sizes, int n_in,
                              void* d_out, int out_size)
{
    const float* x   = (const float*)d_in[0];
    const float* w   = (const float*)d_in[1];
    const float* w1  = (const float*)d_in[2];
    const float* b1  = (const float*)d_in[3];
    const float* a1w = (const float*)d_in[4];
    const float* a1b = (const float*)d_in[5];
    const float* w2  = (const float*)d_in[6];
    const float* b2  = (const float*)d_in[7];
    const float* a2w = (const float*)d_in[8];
    const float* a2b = (const float*)d_in[9];
    const float* w3  = (const float*)d_in[10];
    const float* b3  = (const float*)d_in[11];
    const float* a3w = (const float*)d_in[12];
    const float* a3b = (const float*)d_in[13];

    float* h_out = (float*)d_out;
    float* rgb_out = h_out + BATCH * CMID * NPIX;

    cudaFuncSetAttribute(conv_mma_kernel<512, true>,
                         cudaFuncAttributeMaxDynamicSharedMemorySize, CONV_SMEM);
    cudaFuncSetAttribute(conv_mma_kernel<256, false>,
                         cudaFuncAttributeMaxDynamicSharedMemorySize, CONV_SMEM);

    styles_kernel<<<BATCH, 512>>>(w, a1w, a1b, a2w, a2b, a3w, a3b, w3);
    demod_kernel<512><<<dim3(CMID, BATCH), 256>>>(w1);
    demod_kernel<256><<<dim3(CMID, BATCH), 256>>>(w2);
    wpack_kernel<512><<<(256 * 512 * 9 + 255) / 256, 256>>>(w1);
    wpack_kernel<256><<<(256 * 256 * 9 + 255) / 256, 256>>>(w2);
    uppack_kernel<<<dim3(HW, 16, BATCH), 256>>>(x);
    zborder_kernel<<<(4 * 516 * 96 + 255) / 256, 256>>>();

    conv_mma_kernel<512, true><<<512, 512, CONV_SMEM>>>(b1, nullptr);
    conv_mma_kernel<256, false><<<512, 512, CONV_SMEM>>>(b2, h_out);

    rgb_kernel<<<dim3(NPIX / 256, BATCH), 256>>>(h_out, b3, rgb_out);
}